// round 15
// baseline (speedup 1.0000x reference)
#include <cuda_runtime.h>
#include <cstdint>

#define SEQ 2048
#define HID 2048
#define NH 32
#define NKV 8
#define HD 64
#define HALF 32
#define SCALE 0.125f

// ---------------- scratch (u32 packed bf16 hi/lo planes) ----------------
__device__ uint32_t g_Xhi[2048 * 1024];
__device__ uint32_t g_Xlo[2048 * 1024];
#define WOFF_Q 0
#define WOFF_K 2097152
#define WOFF_V 2621440
#define WOFF_O 3145728
__device__ uint32_t g_Whi[5242880];
__device__ uint32_t g_Wlo[5242880];
__device__ uint32_t g_Qhi[32 * 2048 * 32];    // [h][s][dpair]
__device__ uint32_t g_Qlo[32 * 2048 * 32];
__device__ uint32_t g_Kthi[8 * 2048 * 32];    // [kh][s][dpair]  (B-frag friendly)
__device__ uint32_t g_Ktlo[8 * 2048 * 32];
__device__ uint32_t g_Vthi[8 * 64 * 1024];    // [kh][d][spair]
__device__ uint32_t g_Vtlo[8 * 64 * 1024];
__device__ uint32_t g_AOhi[2048 * 1024];      // [s][hdpair]
__device__ uint32_t g_AOlo[2048 * 1024];
__device__ float    g_invl[NH * SEQ];

// ---------------- helpers ----------------
__device__ __forceinline__ void split_pack(float x0, float x1,
                                           uint32_t& hp, uint32_t& lp)
{
    asm("cvt.rn.bf16x2.f32 %0, %1, %2;" : "=r"(hp) : "f"(x1), "f"(x0));
    float h0 = __uint_as_float(hp << 16);
    float h1 = __uint_as_float(hp & 0xffff0000u);
    float l0 = x0 - h0;
    float l1 = x1 - h1;
    asm("cvt.rn.bf16x2.f32 %0, %1, %2;" : "=r"(lp) : "f"(l1), "f"(l0));
}

__device__ __forceinline__ void mma_bf16(float* d, const uint32_t* a, const uint32_t* b)
{
    asm volatile(
        "mma.sync.aligned.m16n8k16.row.col.f32.bf16.bf16.f32 "
        "{%0,%1,%2,%3}, {%4,%5,%6,%7}, {%8,%9}, {%0,%1,%2,%3};\n"
        : "+f"(d[0]), "+f"(d[1]), "+f"(d[2]), "+f"(d[3])
        : "r"(a[0]), "r"(a[1]), "r"(a[2]), "r"(a[3]), "r"(b[0]), "r"(b[1]));
}

__device__ __forceinline__ void ldsm_x4(uint32_t* r, uint32_t saddr)
{
    asm volatile("ldmatrix.sync.aligned.m8n8.x4.shared.b16 {%0,%1,%2,%3}, [%4];"
                 : "=r"(r[0]), "=r"(r[1]), "=r"(r[2]), "=r"(r[3]) : "r"(saddr));
}

__device__ __forceinline__ void cp16(uint32_t saddr, const void* gptr)
{
    asm volatile("cp.async.cg.shared.global [%0], [%1], 16;" :: "r"(saddr), "l"(gptr));
}
#define CP_COMMIT() asm volatile("cp.async.commit_group;")
#define CP_WAIT0()  asm volatile("cp.async.wait_group 0;")

// exp2 on the FMA pipe (no MUFU)
__device__ __forceinline__ float fast_exp2(float y)
{
    float t = y + 12582912.f;
    float f = y - (t - 12582912.f);
    int   n = __float_as_int(t) << 23;
    float p;
    p = 1.3390776e-3f;
    p = fmaf(p, f, 9.6182376e-3f);
    p = fmaf(p, f, 5.5503573e-2f);
    p = fmaf(p, f, 2.4022649e-1f);
    p = fmaf(p, f, 6.9314720e-1f);
    p = fmaf(p, f, 1.0f);
    return __int_as_float(__float_as_int(p) + n);
}

// ---------------- pack kernels (2 kp-rows per thread) ----
__global__ void pack_rows_kernel(const float* __restrict__ src,
                                 uint32_t* __restrict__ hi,
                                 uint32_t* __restrict__ lo, int N)
{
    int n = blockIdx.y * 256 + threadIdx.x;
    int kp0 = blockIdx.x * 2;
    float x0 = src[(size_t)(2 * kp0) * N + n];
    float x1 = src[(size_t)(2 * kp0 + 1) * N + n];
    float x2 = src[(size_t)(2 * kp0 + 2) * N + n];
    float x3 = src[(size_t)(2 * kp0 + 3) * N + n];
    uint32_t hp, lp;
    split_pack(x0, x1, hp, lp);
    hi[(size_t)kp0 * N + n] = hp;
    lo[(size_t)kp0 * N + n] = lp;
    split_pack(x2, x3, hp, lp);
    hi[(size_t)(kp0 + 1) * N + n] = hp;
    lo[(size_t)(kp0 + 1) * N + n] = lp;
}

__global__ void pack_cols_kernel(const float4* __restrict__ src,
                                 uint2* __restrict__ hi,
                                 uint2* __restrict__ lo)
{
    int idx = blockIdx.x * 512 + threadIdx.x;
    float4 v0 = src[idx];
    float4 v1 = src[idx + 256];
    uint32_t h0, l0, h1, l1;
    split_pack(v0.x, v0.y, h0, l0);
    split_pack(v0.z, v0.w, h1, l1);
    hi[idx] = make_uint2(h0, h1);
    lo[idx] = make_uint2(l0, l1);
    split_pack(v1.x, v1.y, h0, l0);
    split_pack(v1.z, v1.w, h1, l1);
    hi[idx + 256] = make_uint2(h0, h1);
    lo[idx + 256] = make_uint2(l0, l1);
}

// ---------------- GEMM body (device fn, cp.async double-buffered) -----------
template<int TN, int MODE>
__device__ __forceinline__ void gemm_body(
    int bx, int by,
    const uint32_t* __restrict__ Ahi_g, const uint32_t* __restrict__ Alo_g,
    const uint32_t* __restrict__ B1hi_g, const uint32_t* __restrict__ B1lo_g,
    const uint32_t* __restrict__ B2hi_g, const uint32_t* __restrict__ B2lo_g,
    int ldB,
    float* __restrict__ outF,
    uint32_t* __restrict__ O1hi_g, uint32_t* __restrict__ O1lo_g,
    uint32_t* __restrict__ O2hi_g, uint32_t* __restrict__ O2lo_g,
    const float* __restrict__ cosT, const float* __restrict__ sinT)
{
    extern __shared__ uint32_t sm[];
    constexpr int BSTG = 16 * TN;
    const uint32_t smB = (uint32_t)__cvta_generic_to_shared(sm);

    const int tid = threadIdx.x;
    const int lane = tid & 31, wid = tid >> 5;
    const int wm = wid & 3, wn = wid >> 2;
    const int g = lane >> 2, q = lane & 3;
    const int row0 = bx * 128;
    const bool isK = (MODE != 4) || (by < 8);
    const int col0 = (MODE == 4) ? (by & 7) * 64 : by * TN;
    const uint32_t* Bhi_g = (MODE == 4 && !isK) ? B2hi_g : B1hi_g;
    const uint32_t* Blo_g = (MODE == 4 && !isK) ? B2lo_g : B1lo_g;
    constexpr int NT = TN / 16;

    const int lrow = lane & 15, lkp = (lane >> 4) * 4;
    uint32_t aoff[2];
#pragma unroll
    for (int mt = 0; mt < 2; mt++)
        aoff[mt] = ((wm * 32 + mt * 16 + lrow) * 20 + lkp) * 4;

    float acc[2][NT][4];
#pragma unroll
    for (int mt = 0; mt < 2; mt++)
#pragma unroll
        for (int nt = 0; nt < NT; nt++)
#pragma unroll
            for (int i = 0; i < 4; i++) acc[mt][nt][i] = 0.f;

    const int ar0 = tid >> 2, ak4 = (tid & 3) * 4;
    auto issue_stage = [&](int kp0, int s) {
        uint32_t Aho = (s * 5120) * 4;
        uint32_t Alo_o = (s * 5120 + 2560) * 4;
#pragma unroll
        for (int e = 0; e < 2; e++) {
            int r = ar0 + e * 64;
            size_t ga = (size_t)(row0 + r) * 1024 + kp0 + ak4;
            uint32_t so = (r * 20 + ak4) * 4;
            cp16(smB + Aho + so, Ahi_g + ga);
            cp16(smB + Alo_o + so, Alo_g + ga);
        }
        uint32_t Bho = (10240 + s * 2 * BSTG) * 4;
        uint32_t Blo_o = Bho + BSTG * 4;
#pragma unroll
        for (int e = 0; e < (16 * TN) / 1024; e++) {
            int idx = tid + e * 256;
            int kp = idx / (TN / 4), n4 = (idx % (TN / 4)) * 4;
            int sw = n4 ^ ((kp & 3) << 3);
            size_t gb = (size_t)(kp0 + kp) * ldB + col0 + n4;
            cp16(smB + Bho + (kp * TN + sw) * 4, Bhi_g + gb);
            cp16(smB + Blo_o + (kp * TN + sw) * 4, Blo_g + gb);
        }
        CP_COMMIT();
    };

    issue_stage(0, 0);

    for (int it = 0; it < 64; it++) {
        const int s = it & 1;
        CP_WAIT0();
        __syncthreads();
        if (it + 1 < 64) issue_stage((it + 1) * 16, s ^ 1);

        const uint32_t* Bsh = sm + 10240 + s * 2 * BSTG;
        const uint32_t* Bsl = Bsh + BSTG;
        const uint32_t AshB = smB + (s * 5120) * 4;
        const uint32_t AslB = AshB + 2560 * 4;

#pragma unroll
        for (int kb = 0; kb < 16; kb += 8) {
            uint32_t ah[2][4], al[2][4];
#pragma unroll
            for (int mt = 0; mt < 2; mt++) {
                ldsm_x4(ah[mt], AshB + aoff[mt] + kb * 4);
                ldsm_x4(al[mt], AslB + aoff[mt] + kb * 4);
            }
#pragma unroll
            for (int nt = 0; nt < NT; nt++) {
                int c = wn * (TN / 2) + nt * 8 + g;
                int sc = c ^ (q << 3);
                uint32_t bh[2], bl[2];
                bh[0] = Bsh[(kb + q) * TN + sc];
                bh[1] = Bsh[(kb + q + 4) * TN + sc];
                bl[0] = Bsl[(kb + q) * TN + sc];
                bl[1] = Bsl[(kb + q + 4) * TN + sc];
#pragma unroll
                for (int mt = 0; mt < 2; mt++) {
                    mma_bf16(acc[mt][nt], ah[mt], bh);
                    mma_bf16(acc[mt][nt], ah[mt], bl);
                    mma_bf16(acc[mt][nt], al[mt], bh);
                }
            }
        }
    }
    __syncthreads();

    // ---- epilogue ----
    constexpr int OLD = TN + 4;
    float* Outs = (float*)sm;   // [128][OLD]
#pragma unroll
    for (int mt = 0; mt < 2; mt++)
#pragma unroll
        for (int nt = 0; nt < NT; nt++) {
            int r = wm * 32 + mt * 16 + g;
            int c = wn * (TN / 2) + nt * 8 + 2 * q;
            Outs[r * OLD + c]           = acc[mt][nt][0];
            Outs[r * OLD + c + 1]       = acc[mt][nt][1];
            Outs[(r + 8) * OLD + c]     = acc[mt][nt][2];
            Outs[(r + 8) * OLD + c + 1] = acc[mt][nt][3];
        }
    __syncthreads();

    if constexpr (MODE == 0) {
        for (int e = tid; e < 128 * (TN / 4); e += 256) {
            int r = e / (TN / 4), c4 = (e % (TN / 4)) * 4;
            float4 v = *(float4*)(Outs + r * OLD + c4);
            *(float4*)(outF + (size_t)(row0 + r) * 2048 + col0 + c4) = v;
        }
    } else if constexpr (MODE == 1) {     // Q: RoPE + pack pairs along d
        for (int e = tid; e < 128 * 64; e += 256) {
            int r = e >> 6, dp = e & 63;
            int cl = dp * 2;
            int s = row0 + r;
            int d0 = cl & 63;
            int h = (col0 + cl) >> 6;
            float o0 = Outs[r * OLD + cl], o1 = Outs[r * OLD + cl + 1];
            float c0 = cosT[s * 32 + (d0 & 31)], s0 = sinT[s * 32 + (d0 & 31)];
            float c1 = cosT[s * 32 + ((d0 + 1) & 31)], s1 = sinT[s * 32 + ((d0 + 1) & 31)];
            float v0, v1;
            if (d0 < 32) {
                v0 = o0 * c0 - Outs[r * OLD + cl + 32] * s0;
                v1 = o1 * c1 - Outs[r * OLD + cl + 33] * s1;
            } else {
                v0 = o0 * c0 + Outs[r * OLD + cl - 32] * s0;
                v1 = o1 * c1 + Outs[r * OLD + cl - 31] * s1;
            }
            uint32_t hp, lp;
            split_pack(v0, v1, hp, lp);
            size_t o = ((size_t)h * 2048 + s) * 32 + (d0 >> 1);
            O1hi_g[o] = hp; O1lo_g[o] = lp;
        }
    } else {                              // MODE 4: K (isK, [kh][s][dp]) or V^T
        int kh = by & 7;
        if (isK) {
            for (int e = tid; e < 128 * 32; e += 256) {
                int dp = e & 31, sl = e >> 5;
                int d0 = 2 * dp;
                int s = row0 + sl;
                float o0 = Outs[sl * OLD + d0], o1 = Outs[sl * OLD + d0 + 1];
                float c0 = cosT[s * 32 + (d0 & 31)], s0 = sinT[s * 32 + (d0 & 31)];
                float c1 = cosT[s * 32 + ((d0 + 1) & 31)], s1 = sinT[s * 32 + ((d0 + 1) & 31)];
                float v0, v1;
                if (d0 < 32) {
                    v0 = o0 * c0 - Outs[sl * OLD + d0 + 32] * s0;
                    v1 = o1 * c1 - Outs[sl * OLD + d0 + 33] * s1;
                } else {
                    v0 = o0 * c0 + Outs[sl * OLD + d0 - 32] * s0;
                    v1 = o1 * c1 + Outs[sl * OLD + d0 - 31] * s1;
                }
                uint32_t hp, lp;
                split_pack(v0, v1, hp, lp);
                size_t o = ((size_t)kh * 2048 + s) * 32 + dp;
                O1hi_g[o] = hp; O1lo_g[o] = lp;
            }
        } else {
            for (int e = tid; e < 64 * 64; e += 256) {
                int sp = e & 63, d = e >> 6;
                float v0 = Outs[(2 * sp) * OLD + d];
                float v1 = Outs[(2 * sp + 1) * OLD + d];
                uint32_t hp, lp;
                split_pack(v0, v1, hp, lp);
                size_t o = ((size_t)kh * 64 + d) * 1024 + (row0 >> 1) + sp;
                O2hi_g[o] = hp; O2lo_g[o] = lp;
            }
        }
    }
}

// ---------------- merged QKV projection launch ------------------------------
__global__ void __launch_bounds__(256)
proj_qkv_kernel(const uint32_t* __restrict__ Xh, const uint32_t* __restrict__ Xl,
                const uint32_t* __restrict__ WQh, const uint32_t* __restrict__ WQl,
                const uint32_t* __restrict__ WKh, const uint32_t* __restrict__ WKl,
                const uint32_t* __restrict__ WVh, const uint32_t* __restrict__ WVl,
                uint32_t* __restrict__ Qh, uint32_t* __restrict__ Ql,
                uint32_t* __restrict__ Kth, uint32_t* __restrict__ Ktl,
                uint32_t* __restrict__ Vth, uint32_t* __restrict__ Vtl,
                const float* __restrict__ cosT, const float* __restrict__ sinT)
{
    int idx = blockIdx.x;
    if (idx < 256) {
        gemm_body<128, 1>(idx & 15, idx >> 4, Xh, Xl, WQh, WQl, nullptr, nullptr,
                          2048, nullptr, Qh, Ql, nullptr, nullptr, cosT, sinT);
    } else {
        int j = idx - 256;
        gemm_body<64, 4>(j & 15, j >> 4, Xh, Xl, WKh, WKl, WVh, WVl,
                         512, nullptr, Kth, Ktl, Vth, Vtl, cosT, sinT);
    }
}

// ---------------- Wo GEMM launch --------------------------------------------
__global__ void __launch_bounds__(256)
wo_kernel(const uint32_t* __restrict__ AOh, const uint32_t* __restrict__ AOl,
          const uint32_t* __restrict__ WOh, const uint32_t* __restrict__ WOl,
          float* __restrict__ outF,
          const float* __restrict__ cosT, const float* __restrict__ sinT)
{
    gemm_body<128, 0>(blockIdx.x, blockIdx.y, AOh, AOl, WOh, WOl, nullptr, nullptr,
                      2048, outF, nullptr, nullptr, nullptr, nullptr, cosT, sinT);
}

// ---------------- finalize: normalize LOWER region only ---------------------
__global__ void finalize_weights_kernel(float* __restrict__ w,
                                        const float* __restrict__ invl)
{
    int row = blockIdx.x;
    int i = row & (SEQ - 1);
    float s = invl[row];
    int bound4 = (((i >> 6) + 1) << 6) >> 2;
    float4* p = (float4*)(w + (size_t)row * SEQ);
    for (int j4 = threadIdx.x; j4 < bound4; j4 += blockDim.x) {
        float4 v = p[j4];
        v.x *= s; v.y *= s; v.z *= s; v.w *= s;
        p[j4] = v;
    }
}

// ---------------- attention: ldmatrix B operands, cp.async K/V --------------
#define ATTN_SMEM_BYTES (35200 * 4)

__global__ void __launch_bounds__(256)
attn_kernel(const uint32_t* __restrict__ Qhi_g, const uint32_t* __restrict__ Qlo_g,
            const uint32_t* __restrict__ Khi_g, const uint32_t* __restrict__ Klo_g,
            const uint32_t* __restrict__ Vhi_g, const uint32_t* __restrict__ Vlo_g,
            const float* __restrict__ sinks,
            float* wout,
            uint32_t* __restrict__ AOhi_g, uint32_t* __restrict__ AOlo_g,
            float* __restrict__ invl_out)
{
    extern __shared__ uint32_t asmem[];
    uint32_t* Psh = asmem + 26624;    // P [128 query][32 kp] chunk-xor
    uint32_t* Psl = asmem + 30720;
    float* lpart  = (float*)(asmem + 34816);  // [2][128]
    float* invls  = lpart + 256;              // [128]
    const uint32_t smB = (uint32_t)__cvta_generic_to_shared(asmem);

    const int qt = gridDim.x - 1 - blockIdx.x;   // heavy first
    const int h  = blockIdx.y;
    const int kh = h >> 2;
    const int tid = threadIdx.x;
    const int lane = tid & 31, wid = tid >> 5;
    const int wm = wid & 3, wn = wid >> 2;
    const int g = lane >> 2, q = lane & 3;
    const float KEXP = SCALE * 1.44269504089f;

    const int lrow = lane & 15, lkp = (lane >> 4) * 4;
    const int bmi = lane >> 3, brr = lane & 7;        // B-ldmatrix: matrix id, row
    const uint32_t QshB = smB;
    const uint32_t QslB = smB + 4608 * 4;
    uint32_t aoffQ[2];
#pragma unroll
    for (int mt = 0; mt < 2; mt++)
        aoffQ[mt] = ((wm * 32 + mt * 16 + lrow) * 36 + lkp) * 4;
    const uint32_t aoffV = ((wm * 16 + lrow) * 36 + lkp) * 4;

    const uint32_t* Kbh = Khi_g + (size_t)kh * 2048 * 32;
    const uint32_t* Kbl = Klo_g + (size_t)kh * 2048 * 32;
    const uint32_t* Vbh = Vhi_g + (size_t)kh * 64 * 1024;
    const uint32_t* Vbl = Vlo_g + (size_t)kh * 64 * 1024;

    // per-warp wout row bases (hoisted)
    float* wrowA[2];
    float* wrowB[2];
#pragma unroll
    for (int mt = 0; mt < 2; mt++) {
        int growA = qt * 128 + wm * 32 + mt * 16 + g;
        wrowA[mt] = wout ? wout + ((size_t)h * SEQ + growA) * SEQ : nullptr;
        wrowB[mt] = wout ? wout + ((size_t)h * SEQ + growA + 8) * SEQ : nullptr;
    }

    const int vd0 = tid >> 3, vsp4 = (tid & 7) * 4;
    auto issue_kv = [&](int kt, int s) {
        // K tile: [64 key][32 kp] u32, 16B chunks xor-swizzled by (key&7)
        uint32_t Kho = (9216 + s * 4096) * 4;
        uint32_t Klo_o = Kho + 2048 * 4;
#pragma unroll
        for (int e = 0; e < 2; e++) {
            int idx = tid + e * 256;          // 0..511 chunk copies per plane
            int key = idx >> 3, cj = idx & 7;
            int sc = 4 * (cj ^ (key & 7));
            uint32_t so = (key * 32 + sc) * 4;
            size_t gk = (size_t)(kt * 64 + key) * 32 + cj * 4;
            cp16(smB + Kho + so, Kbh + gk);
            cp16(smB + Klo_o + so, Kbl + gk);
        }
        uint32_t Vho = (17408 + s * 4608) * 4;
        uint32_t Vlo_o = Vho + 2304 * 4;
#pragma unroll
        for (int e = 0; e < 2; e++) {
            int d = vd0 + e * 32;
            size_t gv = (size_t)d * 1024 + kt * 32 + vsp4;
            cp16(smB + Vho + (d * 36 + vsp4) * 4, Vbh + gv);
            cp16(smB + Vlo_o + (d * 36 + vsp4) * 4, Vbl + gv);
        }
        CP_COMMIT();
    };

    // Q tile copy
    {
        const uint32_t* Qbh = Qhi_g + ((size_t)h * 2048 + qt * 128) * 32;
        const uint32_t* Qbl = Qlo_g + ((size_t)h * 2048 + qt * 128) * 32;
        uint32_t* Qsh = asmem;
        uint32_t* Qsl = asmem + 4608;
#pragma unroll
        for (int e = 0; e < 4; e++) {
            int idx = tid + e * 256;
            int r = idx >> 3, c4 = (idx & 7) * 4;
            *(uint4*)(Qsh + r * 36 + c4) = *(const uint4*)(Qbh + r * 32 + c4);
            *(uint4*)(Qsl + r * 36 + c4) = *(const uint4*)(Qbl + r * 32 + c4);
        }
    }

    float oacc[8][4];
#pragma unroll
    for (int nt = 0; nt < 8; nt++)
#pragma unroll
        for (int i = 0; i < 4; i++) oacc[nt][i] = 0.f;
    float lsum[2][2] = {{0.f, 0.f}, {0.f, 0.f}};

    issue_kv(0, 0);
    const int ktmax = 2 * qt + 1;

    for (int kt = 0; kt <= ktmax; kt++) {
        const int s = kt & 1;
        CP_WAIT0();
        __syncthreads();
        if (kt < ktmax) issue_kv(kt + 1, s ^ 1);

        const uint32_t KhiB = smB + (9216 + s * 4096) * 4;
        const uint32_t VshB = smB + (17408 + s * 4608) * 4;
        const uint32_t VslB = VshB + 2304 * 4;

        // ---- S = Q @ K^T (B via ldmatrix) ----
        float sacc[2][4][4];
#pragma unroll
        for (int mt = 0; mt < 2; mt++)
#pragma unroll
            for (int nt = 0; nt < 4; nt++)
#pragma unroll
                for (int i = 0; i < 4; i++) sacc[mt][nt][i] = 0.f;
#pragma unroll
        for (int kb0 = 0; kb0 < 32; kb0 += 16) {
            uint32_t ah0[2][4], al0[2][4], ah1[2][4], al1[2][4];
#pragma unroll
            for (int mt = 0; mt < 2; mt++) {
                ldsm_x4(ah0[mt], QshB + aoffQ[mt] + kb0 * 4);
                ldsm_x4(al0[mt], QslB + aoffQ[mt] + kb0 * 4);
                ldsm_x4(ah1[mt], QshB + aoffQ[mt] + (kb0 + 8) * 4);
                ldsm_x4(al1[mt], QslB + aoffQ[mt] + (kb0 + 8) * 4);
            }
#pragma unroll
            for (int nt = 0; nt < 4; nt++) {
                uint32_t bh4[4], bl4[4];
                uint32_t ba = KhiB + (((wn * 32 + nt * 8 + brr) * 32)
                                      + 4 * (((kb0 >> 2) + bmi) ^ brr)) * 4;
                ldsm_x4(bh4, ba);
                ldsm_x4(bl4, ba + 2048 * 4);
#pragma unroll
                for (int mt = 0; mt < 2; mt++) {
                    mma_bf16(sacc[mt][nt], ah0[mt], bh4);
                    mma_bf16(sacc[mt][nt], ah0[mt], bl4);
                    mma_bf16(sacc[mt][nt], al0[mt], bh4);
                    mma_bf16(sacc[mt][nt], ah1[mt], bh4 + 2);
                    mma_bf16(sacc[mt][nt], ah1[mt], bl4 + 2);
                    mma_bf16(sacc[mt][nt], al1[mt], bh4 + 2);
                }
            }
        }

        // ---- exp + mask + store P [query][kp] + wout ----
        const bool diag = (kt >= 2 * qt);
#pragma unroll
        for (int mt = 0; mt < 2; mt++) {
            const int growA = qt * 128 + wm * 32 + mt * 16 + g;
            const int growB = growA + 8;
            const int colA = wm * 32 + mt * 16 + g;
#pragma unroll
            for (int nt = 0; nt < 4; nt++) {
                int lcol = wn * 32 + nt * 8 + 2 * q;
                int gcol = kt * 64 + lcol;
                float w0 = fast_exp2(sacc[mt][nt][0] * KEXP);
                float w1 = fast_exp2(sacc[mt][nt][1] * KEXP);
                float w2 = fast_exp2(sacc[mt][nt][2] * KEXP);
                float w3 = fast_exp2(sacc[mt][nt][3] * KEXP);
                if (diag) {
                    if (gcol > growA)     w0 = 0.f;
                    if (gcol + 1 > growA) w1 = 0.f;
                    if (gcol > growB)     w2 = 0.f;
                    if (gcol + 1 > growB) w3 = 0.f;
                }
                lsum[mt][0] += w0 + w1;
                lsum[mt][1] += w2 + w3;
                if (wout) {
                    *((float2*)(wrowA[mt] + gcol)) = make_float2(w0, w1);
                    *((float2*)(wrowB[mt] + gcol)) = make_float2(w2, w3);
                }
                int pr = lcol >> 1;
                int scol = 4 * ((pr >> 2) ^ (colA & 7)) + (pr & 3);
                uint32_t hp, lp;
                split_pack(w0, w1, hp, lp);
                Psh[colA * 32 + scol] = hp;
                Psl[colA * 32 + scol] = lp;
                split_pack(w2, w3, hp, lp);
                Psh[(colA + 8) * 32 + scol] = hp;
                Psl[(colA + 8) * 32 + scol] = lp;
            }
        }
        __syncthreads();   // P visible

        // ---- O^T += V^T @ P^T (B via ldmatrix) ----
        const uint32_t PhiB = smB + 26624 * 4;
#pragma unroll
        for (int kb0 = 0; kb0 < 32; kb0 += 16) {
            uint32_t avh0[4], avl0[4], avh1[4], avl1[4];
            ldsm_x4(avh0, VshB + aoffV + kb0 * 4);
            ldsm_x4(avl0, VslB + aoffV + kb0 * 4);
            ldsm_x4(avh1, VshB + aoffV + (kb0 + 8) * 4);
            ldsm_x4(avl1, VslB + aoffV + (kb0 + 8) * 4);
#pragma unroll
            for (int nt = 0; nt < 8; nt++) {
                uint32_t bh4[4], bl4[4];
                uint32_t ba = PhiB + (((wn * 64 + nt * 8 + brr) * 32)
                                      + 4 * (((kb0 >> 2) + bmi) ^ brr)) * 4;
                ldsm_x4(bh4, ba);
                ldsm_x4(bl4, ba + 4096 * 4);
                mma_bf16(oacc[nt], avh0, bh4);
                mma_bf16(oacc[nt], avh0, bl4);
                mma_bf16(oacc[nt], avl0, bh4);
                mma_bf16(oacc[nt], avh1, bh4 + 2);
                mma_bf16(oacc[nt], avh1, bl4 + 2);
                mma_bf16(oacc[nt], avl1, bh4 + 2);
            }
        }
    }
    __syncthreads();

    // ---- row sums -> invl (with sink) ----
#pragma unroll
    for (int mt = 0; mt < 2; mt++)
#pragma unroll
        for (int hf = 0; hf < 2; hf++) {
            lsum[mt][hf] += __shfl_xor_sync(0xffffffffu, lsum[mt][hf], 1);
            lsum[mt][hf] += __shfl_xor_sync(0xffffffffu, lsum[mt][hf], 2);
        }
    if (q == 0) {
#pragma unroll
        for (int mt = 0; mt < 2; mt++) {
            lpart[wn * 128 + wm * 32 + mt * 16 + g]     = lsum[mt][0];
            lpart[wn * 128 + wm * 32 + mt * 16 + g + 8] = lsum[mt][1];
        }
    }
    __syncthreads();
    if (tid < 128) {
        float sk = __expf(sinks[h]);
        float iv = 1.f / (lpart[tid] + lpart[128 + tid] + sk);
        invls[tid] = iv;
        invl_out[(size_t)h * SEQ + qt * 128 + tid] = iv;
    }
    __syncthreads();

    // ---- stage O^T into smem as [q][d], then pack AO planes ----
    float* Of = (float*)(asmem + 9216);
#pragma unroll
    for (int nt = 0; nt < 8; nt++) {
        int c0 = wn * 64 + nt * 8 + 2 * q;
        int d0 = wm * 16 + g;
        Of[c0 * 65 + d0]           = oacc[nt][0];
        Of[(c0 + 1) * 65 + d0]     = oacc[nt][1];
        Of[c0 * 65 + d0 + 8]       = oacc[nt][2];
        Of[(c0 + 1) * 65 + d0 + 8] = oacc[nt][3];
    }
    __syncthreads();

    for (int t = tid; t < 128 * 32; t += 256) {
        int qq = t >> 5, dp = t & 31;
        float iv = invls[qq];
        float v0 = Of[qq * 65 + 2 * dp] * iv;
        float v1 = Of[qq * 65 + 2 * dp + 1] * iv;
        uint32_t hp, lp;
        split_pack(v0, v1, hp, lp);
        size_t o = (size_t)(qt * 128 + qq) * 1024 + h * 32 + dp;
        AOhi_g[o] = hp; AOlo_g[o] = lp;
    }

    // ---- zero-fill strictly-upper region for this block's rows ----
    if (wout) {
        const int startc = (qt + 1) * 128;
        const int zc4 = (SEQ - startc) >> 2;
        if (zc4 > 0) {
            const float4 z = make_float4(0.f, 0.f, 0.f, 0.f);
            float* base = wout + ((size_t)h * SEQ + qt * 128) * SEQ + startc;
            for (int t = tid; t < 128 * zc4; t += 256) {
                int r = t / zc4, c4 = t - r * zc4;
                *(float4*)(base + (size_t)r * SEQ + c4 * 4) = z;
            }
        }
    }
}

// ---------------------------------------------------------------------------
extern "C" void kernel_launch(void* const* d_in, const int* in_sizes, int n_in,
                              void* d_out, int out_size)
{
    const float* X     = (const float*)d_in[0];
    const float* cosT  = (const float*)d_in[1];
    const float* sinT  = (const float*)d_in[2];
    const float* Wq    = (const float*)d_in[4];
    const float* Wk    = (const float*)d_in[5];
    const float* Wv    = (const float*)d_in[6];
    const float* Wo    = (const float*)d_in[7];
    const float* sinks = (const float*)d_in[8];

    float* out = (float*)d_out;
    const size_t AO_ELEMS = (size_t)SEQ * HID;
    const size_t W_ELEMS  = (size_t)NH * SEQ * SEQ;
    float* wout = ((size_t)out_size >= AO_ELEMS + W_ELEMS) ? out + AO_ELEMS : nullptr;

    uint32_t *Xh, *Xl, *Wh, *Wl, *Qh, *Ql, *Kth, *Ktl, *Vth, *Vtl, *AOh, *AOl;
    float *ILd;
    cudaGetSymbolAddress((void**)&Xh,  g_Xhi);  cudaGetSymbolAddress((void**)&Xl,  g_Xlo);
    cudaGetSymbolAddress((void**)&Wh,  g_Whi);  cudaGetSymbolAddress((void**)&Wl,  g_Wlo);
    cudaGetSymbolAddress((void**)&Qh,  g_Qhi);  cudaGetSymbolAddress((void**)&Ql,  g_Qlo);
    cudaGetSymbolAddress((void**)&Kth, g_Kthi); cudaGetSymbolAddress((void**)&Ktl, g_Ktlo);
    cudaGetSymbolAddress((void**)&Vth, g_Vthi); cudaGetSymbolAddress((void**)&Vtl, g_Vtlo);
    cudaGetSymbolAddress((void**)&AOh, g_AOhi); cudaGetSymbolAddress((void**)&AOl, g_AOlo);
    cudaGetSymbolAddress((void**)&ILd, g_invl);

    const int SM128 = (10240 + 4 * 16 * 128) * 4;   // 73728 B
    cudaFuncSetAttribute(proj_qkv_kernel, cudaFuncAttributeMaxDynamicSharedMemorySize, SM128);
    cudaFuncSetAttribute(wo_kernel,       cudaFuncAttributeMaxDynamicSharedMemorySize, SM128);
    cudaFuncSetAttribute(attn_kernel, cudaFuncAttributeMaxDynamicSharedMemorySize, ATTN_SMEM_BYTES);

    // one-time side-stream + events for the finalize || wo overlap
    static cudaStream_t s1 = nullptr;
    static cudaEvent_t evFork = nullptr, evJoin = nullptr;
    if (s1 == nullptr) {
        cudaStreamCreateWithFlags(&s1, cudaStreamNonBlocking);
        cudaEventCreateWithFlags(&evFork, cudaEventDisableTiming);
        cudaEventCreateWithFlags(&evJoin, cudaEventDisableTiming);
    }

    // ---- pack weights + X ----
    pack_rows_kernel<<<dim3(512, 8), 256>>>(Wq, Wh + WOFF_Q, Wl + WOFF_Q, 2048);
    pack_rows_kernel<<<dim3(512, 2), 256>>>(Wk, Wh + WOFF_K, Wl + WOFF_K, 512);
    pack_rows_kernel<<<dim3(512, 2), 256>>>(Wv, Wh + WOFF_V, Wl + WOFF_V, 512);
    pack_rows_kernel<<<dim3(512, 8), 256>>>(Wo, Wh + WOFF_O, Wl + WOFF_O, 2048);
    pack_cols_kernel<<<2048, 256>>>((const float4*)X, (uint2*)Xh, (uint2*)Xl);

    // ---- merged Q + K/V projections ----
    proj_qkv_kernel<<<512, 256, SM128>>>(Xh, Xl,
                                         Wh + WOFF_Q, Wl + WOFF_Q,
                                         Wh + WOFF_K, Wl + WOFF_K,
                                         Wh + WOFF_V, Wl + WOFF_V,
                                         Qh, Ql, Kth, Ktl, Vth, Vtl, cosT, sinT);

    // ---- attention (zero-fills upper W region, writes invl) ----
    attn_kernel<<<dim3(SEQ / 128, NH), 256, ATTN_SMEM_BYTES>>>(Qh, Ql, Kth, Ktl, Vth, Vtl,
                                                               sinks, wout, AOh, AOl, ILd);

    if (wout) {
        cudaEventRecord(evFork, 0);
        cudaStreamWaitEvent(s1, evFork, 0);
        finalize_weights_kernel<<<NH * SEQ, 256, 0, s1>>>(wout, ILd);
        wo_kernel<<<dim3(16, 16), 256, SM128>>>(AOh, AOl, Wh + WOFF_O, Wl + WOFF_O,
                                                out, cosT, sinT);
        cudaEventRecord(evJoin, s1);
        cudaStreamWaitEvent(0, evJoin, 0);
    } else {
        wo_kernel<<<dim3(16, 16), 256, SM128>>>(AOh, AOl, Wh + WOFF_O, Wl + WOFF_O,
                                                out, cosT, sinT);
    }
}

// round 16
// speedup vs baseline: 1.1231x; 1.1231x over previous
#include <cuda_runtime.h>
#include <cstdint>

#define SEQ 2048
#define HID 2048
#define NH 32
#define NKV 8
#define HD 64
#define HALF 32
#define SCALE 0.125f

// ---------------- scratch (u32 packed bf16 hi/lo planes) ----------------
__device__ uint32_t g_Xhi[2048 * 1024];
__device__ uint32_t g_Xlo[2048 * 1024];
#define WOFF_Q 0
#define WOFF_K 2097152
#define WOFF_V 2621440
#define WOFF_O 3145728
__device__ uint32_t g_Whi[5242880];
__device__ uint32_t g_Wlo[5242880];
__device__ uint32_t g_Qhi[32 * 2048 * 32];    // [h][s][dpair]
__device__ uint32_t g_Qlo[32 * 2048 * 32];
__device__ uint32_t g_Kthi[8 * 32 * 2048];    // [kh][dpair][s]
__device__ uint32_t g_Ktlo[8 * 32 * 2048];
__device__ uint32_t g_Vthi[8 * 64 * 1024];    // [kh][d][spair]
__device__ uint32_t g_Vtlo[8 * 64 * 1024];
__device__ uint32_t g_AOhi[2048 * 1024];      // [s][hdpair]
__device__ uint32_t g_AOlo[2048 * 1024];
__device__ float    g_invl[NH * SEQ];

// ---------------- helpers ----------------
__device__ __forceinline__ void split_pack(float x0, float x1,
                                           uint32_t& hp, uint32_t& lp)
{
    asm("cvt.rn.bf16x2.f32 %0, %1, %2;" : "=r"(hp) : "f"(x1), "f"(x0));
    float h0 = __uint_as_float(hp << 16);
    float h1 = __uint_as_float(hp & 0xffff0000u);
    float l0 = x0 - h0;
    float l1 = x1 - h1;
    asm("cvt.rn.bf16x2.f32 %0, %1, %2;" : "=r"(lp) : "f"(l1), "f"(l0));
}

__device__ __forceinline__ void mma_bf16(float* d, const uint32_t* a, const uint32_t* b)
{
    asm volatile(
        "mma.sync.aligned.m16n8k16.row.col.f32.bf16.bf16.f32 "
        "{%0,%1,%2,%3}, {%4,%5,%6,%7}, {%8,%9}, {%0,%1,%2,%3};\n"
        : "+f"(d[0]), "+f"(d[1]), "+f"(d[2]), "+f"(d[3])
        : "r"(a[0]), "r"(a[1]), "r"(a[2]), "r"(a[3]), "r"(b[0]), "r"(b[1]));
}

__device__ __forceinline__ void ldsm_x4(uint32_t* r, uint32_t saddr)
{
    asm volatile("ldmatrix.sync.aligned.m8n8.x4.shared.b16 {%0,%1,%2,%3}, [%4];"
                 : "=r"(r[0]), "=r"(r[1]), "=r"(r[2]), "=r"(r[3]) : "r"(saddr));
}

__device__ __forceinline__ void cp16(uint32_t saddr, const void* gptr)
{
    asm volatile("cp.async.cg.shared.global [%0], [%1], 16;" :: "r"(saddr), "l"(gptr));
}
#define CP_COMMIT() asm volatile("cp.async.commit_group;")
#define CP_WAIT0()  asm volatile("cp.async.wait_group 0;")

// exp2 on the FMA pipe (no MUFU)
__device__ __forceinline__ float fast_exp2(float y)
{
    float t = y + 12582912.f;
    float f = y - (t - 12582912.f);
    int   n = __float_as_int(t) << 23;
    float p;
    p = 1.3390776e-3f;
    p = fmaf(p, f, 9.6182376e-3f);
    p = fmaf(p, f, 5.5503573e-2f);
    p = fmaf(p, f, 2.4022649e-1f);
    p = fmaf(p, f, 6.9314720e-1f);
    p = fmaf(p, f, 1.0f);
    return __int_as_float(__float_as_int(p) + n);
}

// ---------------- pack kernels (2 kp-rows per thread) ----
__global__ void pack_rows_kernel(const float* __restrict__ src,
                                 uint32_t* __restrict__ hi,
                                 uint32_t* __restrict__ lo, int N)
{
    int n = blockIdx.y * 256 + threadIdx.x;
    int kp0 = blockIdx.x * 2;
    float x0 = src[(size_t)(2 * kp0) * N + n];
    float x1 = src[(size_t)(2 * kp0 + 1) * N + n];
    float x2 = src[(size_t)(2 * kp0 + 2) * N + n];
    float x3 = src[(size_t)(2 * kp0 + 3) * N + n];
    uint32_t hp, lp;
    split_pack(x0, x1, hp, lp);
    hi[(size_t)kp0 * N + n] = hp;
    lo[(size_t)kp0 * N + n] = lp;
    split_pack(x2, x3, hp, lp);
    hi[(size_t)(kp0 + 1) * N + n] = hp;
    lo[(size_t)(kp0 + 1) * N + n] = lp;
}

__global__ void pack_cols_kernel(const float4* __restrict__ src,
                                 uint2* __restrict__ hi,
                                 uint2* __restrict__ lo)
{
    int idx = blockIdx.x * 512 + threadIdx.x;
    float4 v0 = src[idx];
    float4 v1 = src[idx + 256];
    uint32_t h0, l0, h1, l1;
    split_pack(v0.x, v0.y, h0, l0);
    split_pack(v0.z, v0.w, h1, l1);
    hi[idx] = make_uint2(h0, h1);
    lo[idx] = make_uint2(l0, l1);
    split_pack(v1.x, v1.y, h0, l0);
    split_pack(v1.z, v1.w, h1, l1);
    hi[idx + 256] = make_uint2(h0, h1);
    lo[idx + 256] = make_uint2(l0, l1);
}

// ---------------- GEMM body (device fn, cp.async double-buffered) -----------
template<int TN, int MODE>
__device__ __forceinline__ void gemm_body(
    int bx, int by,
    const uint32_t* __restrict__ Ahi_g, const uint32_t* __restrict__ Alo_g,
    const uint32_t* __restrict__ B1hi_g, const uint32_t* __restrict__ B1lo_g,
    const uint32_t* __restrict__ B2hi_g, const uint32_t* __restrict__ B2lo_g,
    int ldB,
    float* __restrict__ outF,
    uint32_t* __restrict__ O1hi_g, uint32_t* __restrict__ O1lo_g,
    uint32_t* __restrict__ O2hi_g, uint32_t* __restrict__ O2lo_g,
    const float* __restrict__ cosT, const float* __restrict__ sinT)
{
    extern __shared__ uint32_t sm[];
    constexpr int BSTG = 16 * TN;
    const uint32_t smB = (uint32_t)__cvta_generic_to_shared(sm);

    const int tid = threadIdx.x;
    const int lane = tid & 31, wid = tid >> 5;
    const int wm = wid & 3, wn = wid >> 2;
    const int g = lane >> 2, q = lane & 3;
    const int row0 = bx * 128;
    const bool isK = (MODE != 4) || (by < 8);
    const int col0 = (MODE == 4) ? (by & 7) * 64 : by * TN;
    const uint32_t* Bhi_g = (MODE == 4 && !isK) ? B2hi_g : B1hi_g;
    const uint32_t* Blo_g = (MODE == 4 && !isK) ? B2lo_g : B1lo_g;
    constexpr int NT = TN / 16;

    const int lrow = lane & 15, lkp = (lane >> 4) * 4;
    uint32_t aoff[2];
#pragma unroll
    for (int mt = 0; mt < 2; mt++)
        aoff[mt] = ((wm * 32 + mt * 16 + lrow) * 20 + lkp) * 4;

    float acc[2][NT][4];
#pragma unroll
    for (int mt = 0; mt < 2; mt++)
#pragma unroll
        for (int nt = 0; nt < NT; nt++)
#pragma unroll
            for (int i = 0; i < 4; i++) acc[mt][nt][i] = 0.f;

    const int ar0 = tid >> 2, ak4 = (tid & 3) * 4;
    auto issue_stage = [&](int kp0, int s) {
        uint32_t Aho = (s * 5120) * 4;
        uint32_t Alo_o = (s * 5120 + 2560) * 4;
#pragma unroll
        for (int e = 0; e < 2; e++) {
            int r = ar0 + e * 64;
            size_t ga = (size_t)(row0 + r) * 1024 + kp0 + ak4;
            uint32_t so = (r * 20 + ak4) * 4;
            cp16(smB + Aho + so, Ahi_g + ga);
            cp16(smB + Alo_o + so, Alo_g + ga);
        }
        uint32_t Bho = (10240 + s * 2 * BSTG) * 4;
        uint32_t Blo_o = Bho + BSTG * 4;
#pragma unroll
        for (int e = 0; e < (16 * TN) / 1024; e++) {
            int idx = tid + e * 256;
            int kp = idx / (TN / 4), n4 = (idx % (TN / 4)) * 4;
            int sw = n4 ^ ((kp & 3) << 3);
            size_t gb = (size_t)(kp0 + kp) * ldB + col0 + n4;
            cp16(smB + Bho + (kp * TN + sw) * 4, Bhi_g + gb);
            cp16(smB + Blo_o + (kp * TN + sw) * 4, Blo_g + gb);
        }
        CP_COMMIT();
    };

    issue_stage(0, 0);

    for (int it = 0; it < 64; it++) {
        const int s = it & 1;
        CP_WAIT0();
        __syncthreads();
        if (it + 1 < 64) issue_stage((it + 1) * 16, s ^ 1);

        const uint32_t* Bsh = sm + 10240 + s * 2 * BSTG;
        const uint32_t* Bsl = Bsh + BSTG;
        const uint32_t AshB = smB + (s * 5120) * 4;
        const uint32_t AslB = AshB + 2560 * 4;

#pragma unroll
        for (int kb = 0; kb < 16; kb += 8) {
            uint32_t ah[2][4], al[2][4];
#pragma unroll
            for (int mt = 0; mt < 2; mt++) {
                ldsm_x4(ah[mt], AshB + aoff[mt] + kb * 4);
                ldsm_x4(al[mt], AslB + aoff[mt] + kb * 4);
            }
#pragma unroll
            for (int nt = 0; nt < NT; nt++) {
                int c = wn * (TN / 2) + nt * 8 + g;
                int sc = c ^ (q << 3);
                uint32_t bh[2], bl[2];
                bh[0] = Bsh[(kb + q) * TN + sc];
                bh[1] = Bsh[(kb + q + 4) * TN + sc];
                bl[0] = Bsl[(kb + q) * TN + sc];
                bl[1] = Bsl[(kb + q + 4) * TN + sc];
#pragma unroll
                for (int mt = 0; mt < 2; mt++) {
                    mma_bf16(acc[mt][nt], ah[mt], bh);
                    mma_bf16(acc[mt][nt], ah[mt], bl);
                    mma_bf16(acc[mt][nt], al[mt], bh);
                }
            }
        }
    }
    __syncthreads();

    // ---- epilogue ----
    constexpr int OLD = TN + 4;
    float* Outs = (float*)sm;   // [128][OLD]
#pragma unroll
    for (int mt = 0; mt < 2; mt++)
#pragma unroll
        for (int nt = 0; nt < NT; nt++) {
            int r = wm * 32 + mt * 16 + g;
            int c = wn * (TN / 2) + nt * 8 + 2 * q;
            Outs[r * OLD + c]           = acc[mt][nt][0];
            Outs[r * OLD + c + 1]       = acc[mt][nt][1];
            Outs[(r + 8) * OLD + c]     = acc[mt][nt][2];
            Outs[(r + 8) * OLD + c + 1] = acc[mt][nt][3];
        }
    __syncthreads();

    if constexpr (MODE == 0) {
        for (int e = tid; e < 128 * (TN / 4); e += 256) {
            int r = e / (TN / 4), c4 = (e % (TN / 4)) * 4;
            float4 v = *(float4*)(Outs + r * OLD + c4);
            *(float4*)(outF + (size_t)(row0 + r) * 2048 + col0 + c4) = v;
        }
    } else if constexpr (MODE == 1) {     // Q: RoPE + pack pairs along d
        for (int e = tid; e < 128 * 64; e += 256) {
            int r = e >> 6, dp = e & 63;
            int cl = dp * 2;
            int s = row0 + r;
            int d0 = cl & 63;
            int h = (col0 + cl) >> 6;
            float o0 = Outs[r * OLD + cl], o1 = Outs[r * OLD + cl + 1];
            float c0 = cosT[s * 32 + (d0 & 31)], s0 = sinT[s * 32 + (d0 & 31)];
            float c1 = cosT[s * 32 + ((d0 + 1) & 31)], s1 = sinT[s * 32 + ((d0 + 1) & 31)];
            float v0, v1;
            if (d0 < 32) {
                v0 = o0 * c0 - Outs[r * OLD + cl + 32] * s0;
                v1 = o1 * c1 - Outs[r * OLD + cl + 33] * s1;
            } else {
                v0 = o0 * c0 + Outs[r * OLD + cl - 32] * s0;
                v1 = o1 * c1 + Outs[r * OLD + cl - 31] * s1;
            }
            uint32_t hp, lp;
            split_pack(v0, v1, hp, lp);
            size_t o = ((size_t)h * 2048 + s) * 32 + (d0 >> 1);
            O1hi_g[o] = hp; O1lo_g[o] = lp;
        }
    } else {                              // MODE 4: K^T (isK) or V^T
        int kh = by & 7;
        if (isK) {
            for (int e = tid; e < 128 * 32; e += 256) {
                int sl = e & 127, dp = e >> 7;
                int d0 = 2 * dp;
                int s = row0 + sl;
                float o0 = Outs[sl * OLD + d0], o1 = Outs[sl * OLD + d0 + 1];
                float c0 = cosT[s * 32 + (d0 & 31)], s0 = sinT[s * 32 + (d0 & 31)];
                float c1 = cosT[s * 32 + ((d0 + 1) & 31)], s1 = sinT[s * 32 + ((d0 + 1) & 31)];
                float v0, v1;
                if (d0 < 32) {
                    v0 = o0 * c0 - Outs[sl * OLD + d0 + 32] * s0;
                    v1 = o1 * c1 - Outs[sl * OLD + d0 + 33] * s1;
                } else {
                    v0 = o0 * c0 + Outs[sl * OLD + d0 - 32] * s0;
                    v1 = o1 * c1 + Outs[sl * OLD + d0 - 31] * s1;
                }
                uint32_t hp, lp;
                split_pack(v0, v1, hp, lp);
                size_t o = ((size_t)kh * 32 + dp) * 2048 + s;
                O1hi_g[o] = hp; O1lo_g[o] = lp;
            }
        } else {
            for (int e = tid; e < 64 * 64; e += 256) {
                int sp = e & 63, d = e >> 6;
                float v0 = Outs[(2 * sp) * OLD + d];
                float v1 = Outs[(2 * sp + 1) * OLD + d];
                uint32_t hp, lp;
                split_pack(v0, v1, hp, lp);
                size_t o = ((size_t)kh * 64 + d) * 1024 + (row0 >> 1) + sp;
                O2hi_g[o] = hp; O2lo_g[o] = lp;
            }
        }
    }
}

// ---------------- merged QKV projection launch ------------------------------
__global__ void __launch_bounds__(256)
proj_qkv_kernel(const uint32_t* __restrict__ Xh, const uint32_t* __restrict__ Xl,
                const uint32_t* __restrict__ WQh, const uint32_t* __restrict__ WQl,
                const uint32_t* __restrict__ WKh, const uint32_t* __restrict__ WKl,
                const uint32_t* __restrict__ WVh, const uint32_t* __restrict__ WVl,
                uint32_t* __restrict__ Qh, uint32_t* __restrict__ Ql,
                uint32_t* __restrict__ Kth, uint32_t* __restrict__ Ktl,
                uint32_t* __restrict__ Vth, uint32_t* __restrict__ Vtl,
                const float* __restrict__ cosT, const float* __restrict__ sinT)
{
    int idx = blockIdx.x;
    if (idx < 256) {
        gemm_body<128, 1>(idx & 15, idx >> 4, Xh, Xl, WQh, WQl, nullptr, nullptr,
                          2048, nullptr, Qh, Ql, nullptr, nullptr, cosT, sinT);
    } else {
        int j = idx - 256;
        gemm_body<64, 4>(j & 15, j >> 4, Xh, Xl, WKh, WKl, WVh, WVl,
                         512, nullptr, Kth, Ktl, Vth, Vtl, cosT, sinT);
    }
}

// ---------------- Wo GEMM launch --------------------------------------------
__global__ void __launch_bounds__(256)
wo_kernel(const uint32_t* __restrict__ AOh, const uint32_t* __restrict__ AOl,
          const uint32_t* __restrict__ WOh, const uint32_t* __restrict__ WOl,
          float* __restrict__ outF,
          const float* __restrict__ cosT, const float* __restrict__ sinT)
{
    gemm_body<128, 0>(blockIdx.x, blockIdx.y, AOh, AOl, WOh, WOl, nullptr, nullptr,
                      2048, outF, nullptr, nullptr, nullptr, nullptr, cosT, sinT);
}

// ---------------- finalize: normalize LOWER region only ---------------------
__global__ void finalize_weights_kernel(float* __restrict__ w,
                                        const float* __restrict__ invl)
{
    int row = blockIdx.x;
    int i = row & (SEQ - 1);
    float s = invl[row];
    int bound4 = (((i >> 6) + 1) << 6) >> 2;
    float4* p = (float4*)(w + (size_t)row * SEQ);
    for (int j4 = threadIdx.x; j4 < bound4; j4 += blockDim.x) {
        float4 v = p[j4];
        v.x *= s; v.y *= s; v.z *= s; v.w *= s;
        p[j4] = v;
    }
}

// ---------------- attention: 128-query tiles, cp.async K/V ------------------
#define ATTN_SMEM_BYTES (35200 * 4)

__global__ void __launch_bounds__(256)
attn_kernel(const uint32_t* __restrict__ Qhi_g, const uint32_t* __restrict__ Qlo_g,
            const uint32_t* __restrict__ Khi_g, const uint32_t* __restrict__ Klo_g,
            const uint32_t* __restrict__ Vhi_g, const uint32_t* __restrict__ Vlo_g,
            const float* __restrict__ sinks,
            float* wout,
            uint32_t* __restrict__ AOhi_g, uint32_t* __restrict__ AOlo_g,
            float* __restrict__ invl_out)
{
    extern __shared__ uint32_t asmem[];
    uint32_t* Psh = asmem + 26624;    // P^T [32][128] swz
    uint32_t* Psl = asmem + 30720;
    float* lpart  = (float*)(asmem + 34816);  // [2][128]
    float* invls  = lpart + 256;              // [128]
    const uint32_t smB = (uint32_t)__cvta_generic_to_shared(asmem);

    const int qt = gridDim.x - 1 - blockIdx.x;   // heavy first
    const int h  = blockIdx.y;
    const int kh = h >> 2;
    const int tid = threadIdx.x;
    const int lane = tid & 31, wid = tid >> 5;
    const int wm = wid & 3, wn = wid >> 2;
    const int g = lane >> 2, q = lane & 3;
    const float KEXP = SCALE * 1.44269504089f;

    const int lrow = lane & 15, lkp = (lane >> 4) * 4;
    const uint32_t QshB = smB;
    const uint32_t QslB = smB + 4608 * 4;
    uint32_t aoffQ[2];
#pragma unroll
    for (int mt = 0; mt < 2; mt++)
        aoffQ[mt] = ((wm * 32 + mt * 16 + lrow) * 36 + lkp) * 4;
    const uint32_t aoffV = ((wm * 16 + lrow) * 36 + lkp) * 4;

    const uint32_t* Kbh = Khi_g + (size_t)kh * 32 * 2048;
    const uint32_t* Kbl = Klo_g + (size_t)kh * 32 * 2048;
    const uint32_t* Vbh = Vhi_g + (size_t)kh * 64 * 1024;
    const uint32_t* Vbl = Vlo_g + (size_t)kh * 64 * 1024;

    // per-warp wout row bases (hoisted)
    float* wrowA[2];
    float* wrowB[2];
#pragma unroll
    for (int mt = 0; mt < 2; mt++) {
        int growA = qt * 128 + wm * 32 + mt * 16 + g;
        wrowA[mt] = wout ? wout + ((size_t)h * SEQ + growA) * SEQ : nullptr;
        wrowB[mt] = wout ? wout + ((size_t)h * SEQ + growA + 8) * SEQ : nullptr;
    }

    const int kdp0 = tid >> 4, ks4 = (tid & 15) * 4;
    const int vd0 = tid >> 3, vsp4 = (tid & 7) * 4;
    auto issue_kv = [&](int kt, int s) {
        uint32_t Kho = (9216 + s * 4096) * 4;
        uint32_t Klo_o = Kho + 2048 * 4;
#pragma unroll
        for (int e = 0; e < 2; e++) {
            int dp = kdp0 + e * 16;
            int sw = ks4 ^ ((dp & 3) << 3);
            size_t gk = (size_t)dp * 2048 + kt * 64 + ks4;
            cp16(smB + Kho + (dp * 64 + sw) * 4, Kbh + gk);
            cp16(smB + Klo_o + (dp * 64 + sw) * 4, Kbl + gk);
        }
        uint32_t Vho = (17408 + s * 4608) * 4;
        uint32_t Vlo_o = Vho + 2304 * 4;
#pragma unroll
        for (int e = 0; e < 2; e++) {
            int d = vd0 + e * 32;
            size_t gv = (size_t)d * 1024 + kt * 32 + vsp4;
            cp16(smB + Vho + (d * 36 + vsp4) * 4, Vbh + gv);
            cp16(smB + Vlo_o + (d * 36 + vsp4) * 4, Vbl + gv);
        }
        CP_COMMIT();
    };

    // Q tile copy
    {
        const uint32_t* Qbh = Qhi_g + ((size_t)h * 2048 + qt * 128) * 32;
        const uint32_t* Qbl = Qlo_g + ((size_t)h * 2048 + qt * 128) * 32;
        uint32_t* Qsh = asmem;
        uint32_t* Qsl = asmem + 4608;
#pragma unroll
        for (int e = 0; e < 4; e++) {
            int idx = tid + e * 256;
            int r = idx >> 3, c4 = (idx & 7) * 4;
            *(uint4*)(Qsh + r * 36 + c4) = *(const uint4*)(Qbh + r * 32 + c4);
            *(uint4*)(Qsl + r * 36 + c4) = *(const uint4*)(Qbl + r * 32 + c4);
        }
    }

    float oacc[8][4];
#pragma unroll
    for (int nt = 0; nt < 8; nt++)
#pragma unroll
        for (int i = 0; i < 4; i++) oacc[nt][i] = 0.f;
    float lsum[2][2] = {{0.f, 0.f}, {0.f, 0.f}};

    issue_kv(0, 0);
    const int ktmax = 2 * qt + 1;

    for (int kt = 0; kt <= ktmax; kt++) {
        const int s = kt & 1;
        CP_WAIT0();
        __syncthreads();
        if (kt < ktmax) issue_kv(kt + 1, s ^ 1);

        const uint32_t* Ksh = asmem + 9216 + s * 4096;
        const uint32_t* Ksl = Ksh + 2048;
        const uint32_t VshB = smB + (17408 + s * 4608) * 4;
        const uint32_t VslB = VshB + 2304 * 4;

        // ---- S = Q @ K^T ----
        float sacc[2][4][4];
#pragma unroll
        for (int mt = 0; mt < 2; mt++)
#pragma unroll
            for (int nt = 0; nt < 4; nt++)
#pragma unroll
                for (int i = 0; i < 4; i++) sacc[mt][nt][i] = 0.f;
#pragma unroll
        for (int kb = 0; kb < 32; kb += 8) {
            uint32_t ah[2][4], al[2][4];
#pragma unroll
            for (int mt = 0; mt < 2; mt++) {
                ldsm_x4(ah[mt], QshB + aoffQ[mt] + kb * 4);
                ldsm_x4(al[mt], QslB + aoffQ[mt] + kb * 4);
            }
#pragma unroll
            for (int nt = 0; nt < 4; nt++) {
                int c = wn * 32 + nt * 8 + g;
                int sc = c ^ (q << 3);
                uint32_t bh[2], bl[2];
                bh[0] = Ksh[(kb + q) * 64 + sc];
                bh[1] = Ksh[(kb + q + 4) * 64 + sc];
                bl[0] = Ksl[(kb + q) * 64 + sc];
                bl[1] = Ksl[(kb + q + 4) * 64 + sc];
#pragma unroll
                for (int mt = 0; mt < 2; mt++) {
                    mma_bf16(sacc[mt][nt], ah[mt], bh);
                    mma_bf16(sacc[mt][nt], ah[mt], bl);
                    mma_bf16(sacc[mt][nt], al[mt], bh);
                }
            }
        }

        // ---- exp + mask + store P^T + wout ----
        const bool diag = (kt >= 2 * qt);
#pragma unroll
        for (int mt = 0; mt < 2; mt++) {
            const int growA = qt * 128 + wm * 32 + mt * 16 + g;
            const int growB = growA + 8;
#pragma unroll
            for (int nt = 0; nt < 4; nt++) {
                int lcol = wn * 32 + nt * 8 + 2 * q;
                int gcol = kt * 64 + lcol;
                float w0 = fast_exp2(sacc[mt][nt][0] * KEXP);
                float w1 = fast_exp2(sacc[mt][nt][1] * KEXP);
                float w2 = fast_exp2(sacc[mt][nt][2] * KEXP);
                float w3 = fast_exp2(sacc[mt][nt][3] * KEXP);
                if (diag) {
                    if (gcol > growA)     w0 = 0.f;
                    if (gcol + 1 > growA) w1 = 0.f;
                    if (gcol > growB)     w2 = 0.f;
                    if (gcol + 1 > growB) w3 = 0.f;
                }
                lsum[mt][0] += w0 + w1;
                lsum[mt][1] += w2 + w3;
                if (wout) {
                    *((float2*)(wrowA[mt] + gcol)) = make_float2(w0, w1);
                    *((float2*)(wrowB[mt] + gcol)) = make_float2(w2, w3);
                }
                int pr = lcol >> 1;
                int colA = wm * 32 + mt * 16 + g;
                uint32_t hp, lp;
                split_pack(w0, w1, hp, lp);
                Psh[pr * 128 + (colA ^ ((pr & 3) << 3))] = hp;
                Psl[pr * 128 + (colA ^ ((pr & 3) << 3))] = lp;
                split_pack(w2, w3, hp, lp);
                Psh[pr * 128 + ((colA + 8) ^ ((pr & 3) << 3))] = hp;
                Psl[pr * 128 + ((colA + 8) ^ ((pr & 3) << 3))] = lp;
            }
        }
        __syncthreads();   // P visible

        // ---- O^T += V^T @ P^T ----
#pragma unroll
        for (int kb = 0; kb < 32; kb += 8) {
            uint32_t ah[4], al[4];
            ldsm_x4(ah, VshB + aoffV + kb * 4);
            ldsm_x4(al, VslB + aoffV + kb * 4);
#pragma unroll
            for (int nt = 0; nt < 8; nt++) {
                int c = wn * 64 + nt * 8 + g;
                int sc = c ^ (q << 3);
                uint32_t bh[2], bl[2];
                bh[0] = Psh[(kb + q) * 128 + sc];
                bh[1] = Psh[(kb + q + 4) * 128 + sc];
                bl[0] = Psl[(kb + q) * 128 + sc];
                bl[1] = Psl[(kb + q + 4) * 128 + sc];
                mma_bf16(oacc[nt], ah, bh);
                mma_bf16(oacc[nt], ah, bl);
                mma_bf16(oacc[nt], al, bh);
            }
        }
    }
    __syncthreads();

    // ---- row sums -> invl (with sink) ----
#pragma unroll
    for (int mt = 0; mt < 2; mt++)
#pragma unroll
        for (int hf = 0; hf < 2; hf++) {
            lsum[mt][hf] += __shfl_xor_sync(0xffffffffu, lsum[mt][hf], 1);
            lsum[mt][hf] += __shfl_xor_sync(0xffffffffu, lsum[mt][hf], 2);
        }
    if (q == 0) {
#pragma unroll
        for (int mt = 0; mt < 2; mt++) {
            lpart[wn * 128 + wm * 32 + mt * 16 + g]     = lsum[mt][0];
            lpart[wn * 128 + wm * 32 + mt * 16 + g + 8] = lsum[mt][1];
        }
    }
    __syncthreads();
    if (tid < 128) {
        float sk = __expf(sinks[h]);
        float iv = 1.f / (lpart[tid] + lpart[128 + tid] + sk);
        invls[tid] = iv;
        invl_out[(size_t)h * SEQ + qt * 128 + tid] = iv;
    }
    __syncthreads();

    // ---- stage O^T into smem as [q][d], then pack AO planes ----
    float* Of = (float*)(asmem + 9216);
#pragma unroll
    for (int nt = 0; nt < 8; nt++) {
        int c0 = wn * 64 + nt * 8 + 2 * q;
        int d0 = wm * 16 + g;
        Of[c0 * 65 + d0]           = oacc[nt][0];
        Of[(c0 + 1) * 65 + d0]     = oacc[nt][1];
        Of[c0 * 65 + d0 + 8]       = oacc[nt][2];
        Of[(c0 + 1) * 65 + d0 + 8] = oacc[nt][3];
    }
    __syncthreads();

    for (int t = tid; t < 128 * 32; t += 256) {
        int qq = t >> 5, dp = t & 31;
        float iv = invls[qq];
        float v0 = Of[qq * 65 + 2 * dp] * iv;
        float v1 = Of[qq * 65 + 2 * dp + 1] * iv;
        uint32_t hp, lp;
        split_pack(v0, v1, hp, lp);
        size_t o = (size_t)(qt * 128 + qq) * 1024 + h * 32 + dp;
        AOhi_g[o] = hp; AOlo_g[o] = lp;
    }

    // ---- zero-fill strictly-upper region for this block's rows ----
    if (wout) {
        const int startc = (qt + 1) * 128;
        const int zc4 = (SEQ - startc) >> 2;
        if (zc4 > 0) {
            const float4 z = make_float4(0.f, 0.f, 0.f, 0.f);
            float* base = wout + ((size_t)h * SEQ + qt * 128) * SEQ + startc;
            for (int t = tid; t < 128 * zc4; t += 256) {
                int r = t / zc4, c4 = t - r * zc4;
                *(float4*)(base + (size_t)r * SEQ + c4 * 4) = z;
            }
        }
    }
}

// ---------------------------------------------------------------------------
extern "C" void kernel_launch(void* const* d_in, const int* in_sizes, int n_in,
                              void* d_out, int out_size)
{
    const float* X     = (const float*)d_in[0];
    const float* cosT  = (const float*)d_in[1];
    const float* sinT  = (const float*)d_in[2];
    const float* Wq    = (const float*)d_in[4];
    const float* Wk    = (const float*)d_in[5];
    const float* Wv    = (const float*)d_in[6];
    const float* Wo    = (const float*)d_in[7];
    const float* sinks = (const float*)d_in[8];

    float* out = (float*)d_out;
    const size_t AO_ELEMS = (size_t)SEQ * HID;
    const size_t W_ELEMS  = (size_t)NH * SEQ * SEQ;
    float* wout = ((size_t)out_size >= AO_ELEMS + W_ELEMS) ? out + AO_ELEMS : nullptr;

    uint32_t *Xh, *Xl, *Wh, *Wl, *Qh, *Ql, *Kth, *Ktl, *Vth, *Vtl, *AOh, *AOl;
    float *ILd;
    cudaGetSymbolAddress((void**)&Xh,  g_Xhi);  cudaGetSymbolAddress((void**)&Xl,  g_Xlo);
    cudaGetSymbolAddress((void**)&Wh,  g_Whi);  cudaGetSymbolAddress((void**)&Wl,  g_Wlo);
    cudaGetSymbolAddress((void**)&Qh,  g_Qhi);  cudaGetSymbolAddress((void**)&Ql,  g_Qlo);
    cudaGetSymbolAddress((void**)&Kth, g_Kthi); cudaGetSymbolAddress((void**)&Ktl, g_Ktlo);
    cudaGetSymbolAddress((void**)&Vth, g_Vthi); cudaGetSymbolAddress((void**)&Vtl, g_Vtlo);
    cudaGetSymbolAddress((void**)&AOh, g_AOhi); cudaGetSymbolAddress((void**)&AOl, g_AOlo);
    cudaGetSymbolAddress((void**)&ILd, g_invl);

    const int SM128 = (10240 + 4 * 16 * 128) * 4;   // 73728 B
    cudaFuncSetAttribute(proj_qkv_kernel, cudaFuncAttributeMaxDynamicSharedMemorySize, SM128);
    cudaFuncSetAttribute(wo_kernel,       cudaFuncAttributeMaxDynamicSharedMemorySize, SM128);
    cudaFuncSetAttribute(attn_kernel, cudaFuncAttributeMaxDynamicSharedMemorySize, ATTN_SMEM_BYTES);

    // one-time side-stream + events (capture-safe fork/join, proven in R14)
    static cudaStream_t s1 = nullptr;
    static cudaEvent_t evFork = nullptr, evJoin = nullptr, evFork2 = nullptr, evJoin2 = nullptr;
    if (s1 == nullptr) {
        cudaStreamCreateWithFlags(&s1, cudaStreamNonBlocking);
        cudaEventCreateWithFlags(&evFork, cudaEventDisableTiming);
        cudaEventCreateWithFlags(&evJoin, cudaEventDisableTiming);
        cudaEventCreateWithFlags(&evFork2, cudaEventDisableTiming);
        cudaEventCreateWithFlags(&evJoin2, cudaEventDisableTiming);
    }

    // ---- pack weights + X : fork across two streams ----
    cudaEventRecord(evFork2, 0);
    cudaStreamWaitEvent(s1, evFork2, 0);
    // side stream: Wk, Wv, Wo packs
    pack_rows_kernel<<<dim3(512, 2), 256, 0, s1>>>(Wk, Wh + WOFF_K, Wl + WOFF_K, 512);
    pack_rows_kernel<<<dim3(512, 2), 256, 0, s1>>>(Wv, Wh + WOFF_V, Wl + WOFF_V, 512);
    pack_rows_kernel<<<dim3(512, 8), 256, 0, s1>>>(Wo, Wh + WOFF_O, Wl + WOFF_O, 2048);
    // main stream: Wq, X packs
    pack_rows_kernel<<<dim3(512, 8), 256>>>(Wq, Wh + WOFF_Q, Wl + WOFF_Q, 2048);
    pack_cols_kernel<<<2048, 256>>>((const float4*)X, (uint2*)Xh, (uint2*)Xl);
    cudaEventRecord(evJoin2, s1);
    cudaStreamWaitEvent(0, evJoin2, 0);

    // ---- merged Q + K/V projections ----
    proj_qkv_kernel<<<512, 256, SM128>>>(Xh, Xl,
                                         Wh + WOFF_Q, Wl + WOFF_Q,
                                         Wh + WOFF_K, Wl + WOFF_K,
                                         Wh + WOFF_V, Wl + WOFF_V,
                                         Qh, Ql, Kth, Ktl, Vth, Vtl, cosT, sinT);

    // ---- attention (zero-fills upper W region, writes invl) ----
    attn_kernel<<<dim3(SEQ / 128, NH), 256, ATTN_SMEM_BYTES>>>(Qh, Ql, Kth, Ktl, Vth, Vtl,
                                                               sinks, wout, AOh, AOl, ILd);

    if (wout) {
        cudaEventRecord(evFork, 0);
        cudaStreamWaitEvent(s1, evFork, 0);
        finalize_weights_kernel<<<NH * SEQ, 256, 0, s1>>>(wout, ILd);
        wo_kernel<<<dim3(16, 16), 256, SM128>>>(AOh, AOl, Wh + WOFF_O, Wl + WOFF_O,
                                                out, cosT, sinT);
        cudaEventRecord(evJoin, s1);
        cudaStreamWaitEvent(0, evJoin, 0);
    } else {
        wo_kernel<<<dim3(16, 16), 256, SM128>>>(AOh, AOl, Wh + WOFF_O, Wl + WOFF_O,
                                                out, cosT, sinT);
    }
}